// round 5
// baseline (speedup 1.0000x reference)
#include <cuda_runtime.h>
#include <cuda_bf16.h>
#include <cstdint>

// ============================================================================
//   x : (3, 8192) fp32   W1 : (8192, 64)   W2 : (64, 64)   W3 : (64, 1)
//   out = mean(per_row MLP(corr)) - regu2*sum(x2) - regu*sum(exp(x2/(2 rl^2)))
//   corr[i,j] = sum_c x[c,(i+j)%N] * x[c,i]
//
//   R5: g_partial transposed to [kq][row][f]; MLP epilogue rebuilt as
//   warp-per-row (no register-array spill, coalesced float2 loads).
// ============================================================================
#define NTOK 8192
#define KQUART 2048
#define BANDLEN 2336                     // 2048 + 256 + slack, mult of 32
#define ODD_OFF (3 * BANDLEN + 16)       // +16 floats: disjoint banks vs even

__device__ double g_acc[3];                               // sum_x2, sum_exp, sum_per_row
__device__ unsigned int g_done;                           // mlp completion counter
__device__ __align__(16) float g_partial[4 * NTOK * 64];  // [kq][row][f], 8MB
__device__ __align__(16) uint32_t g_w1p[512 * 32 * 16];   // [ks][lane][nt*2+r] bf16x2

__device__ __forceinline__ uint32_t pack_bf16x2(float lo, float hi) {
    uint32_t r;
    asm("cvt.rn.bf16x2.f32 %0, %1, %2;" : "=r"(r) : "f"(hi), "f"(lo));
    return r;
}
__device__ __forceinline__ float elu1(float v) { return v > 0.f ? v : expm1f(v); }

#define MMA_BF16(d0,d1,d2,d3,a0,a1,a2,a3,b0,b1) \
    asm volatile("mma.sync.aligned.m16n8k16.row.col.f32.bf16.bf16.f32 " \
                 "{%0,%1,%2,%3}, {%4,%5,%6,%7}, {%8,%9}, {%0,%1,%2,%3};" \
                 : "+f"(d0), "+f"(d1), "+f"(d2), "+f"(d3) \
                 : "r"(a0), "r"(a1), "r"(a2), "r"(a3), "r"(b0), "r"(b1))

// ---------------------------------------------------------------------------
// K1: W1 -> m16n8k16 B fragments (coalesced via smem). Block 0 zeroes accums.
// ---------------------------------------------------------------------------
__global__ __launch_bounds__(256) void w1prep_kernel(const float* __restrict__ W1) {
    __shared__ float w[2048];
    if (blockIdx.x == 0 && threadIdx.x == 0) {
        g_acc[0] = 0.0; g_acc[1] = 0.0; g_acc[2] = 0.0; g_done = 0u;
    }
    const int b = blockIdx.x, tid = threadIdx.x;
    const float* src = W1 + b * 2048;                 // rows [32b, 32b+32) x 64
    #pragma unroll
    for (int i = 0; i < 8; i++) w[tid + i * 256] = src[tid + i * 256];
    __syncthreads();

    uint32_t o4[4];
    #pragma unroll
    for (int j = 0; j < 4; j++) {
        const int o = tid * 4 + j;                    // 0..1023
        const int ksl = o >> 9;
        const int rest = o & 511;
        const int lane = rest >> 4;
        const int q = rest & 15;
        const int nt = q >> 1, r = q & 1;
        const int k = ksl * 16 + (lane & 3) * 2 + r * 8;
        const int n = nt * 8 + (lane >> 2);
        o4[j] = pack_bf16x2(w[k * 64 + n], w[(k + 1) * 64 + n]);
    }
    ((uint4*)g_w1p)[b * 256 + tid] = make_uint4(o4[0], o4[1], o4[2], o4[3]);
}

// ---------------------------------------------------------------------------
// K2: regularization reductions
// ---------------------------------------------------------------------------
__global__ void reg_kernel(const float* __restrict__ x, const float* __restrict__ rl_p) {
    __shared__ float s1[32], s2[32];
    const int i = blockIdx.x * 1024 + threadIdx.x;
    const float a = x[i], b = x[NTOK + i], c = x[2 * NTOK + i];
    float x2 = fmaf(a, a, fmaf(b, b, c * c));
    const float rl = rl_p[0];
    float e = expf(x2 / (2.f * rl * rl));
    #pragma unroll
    for (int o = 16; o > 0; o >>= 1) {
        x2 += __shfl_down_sync(0xFFFFFFFFu, x2, o);
        e  += __shfl_down_sync(0xFFFFFFFFu, e, o);
    }
    const int warp = threadIdx.x >> 5, lane = threadIdx.x & 31;
    if (lane == 0) { s1[warp] = x2; s2[warp] = e; }
    __syncthreads();
    if (warp == 0) {
        float v1 = s1[lane], v2 = s2[lane];
        #pragma unroll
        for (int o = 16; o > 0; o >>= 1) {
            v1 += __shfl_down_sync(0xFFFFFFFFu, v1, o);
            v2 += __shfl_down_sync(0xFFFFFFFFu, v2, o);
        }
        if (lane == 0) {
            atomicAdd(&g_acc[0], (double)v1);
            atomicAdd(&g_acc[1], (double)v2);
        }
    }
}

// ---------------------------------------------------------------------------
// K3: fused corr-build + mma.sync bf16 GEMM (preact = corr @ W1)
//   grid = 128: (i-tile of 256 rows) x (K-quarter of 2048)
//   warp owns 32 rows = 2 m16-strips; 6 LDS.64/step feed 16 HMMAs.
// ---------------------------------------------------------------------------
__global__ __launch_bounds__(256, 1) void gemm_kernel(const float* __restrict__ x) {
    extern __shared__ float band[];                   // even[3][BANDLEN] | pad16 | odd[3][BANDLEN]
    const int tid = threadIdx.x, warp = tid >> 5, lane = tid & 31;
    const int g = lane >> 2, t = lane & 3;
    const int it = blockIdx.x >> 2, kq = blockIdx.x & 3;
    const int i0 = it * 256, jbase = kq * KQUART;

    for (int o = tid; o < BANDLEN; o += 256) {
        const int s0 = (i0 + jbase + o) & (NTOK - 1);
        const int s1 = (i0 + jbase + o + 1) & (NTOK - 1);
        band[o]                         = x[s0];
        band[BANDLEN + o]               = x[NTOK + s0];
        band[2 * BANDLEN + o]           = x[2 * NTOK + s0];
        band[ODD_OFF + o]               = x[s1];
        band[ODD_OFF + BANDLEN + o]     = x[NTOK + s1];
        band[ODD_OFF + 2 * BANDLEN + o] = x[2 * NTOK + s1];
    }
    const int r0 = i0 + warp * 32 + g;
    const float xA0 = x[r0],      xA1 = x[NTOK + r0],      xA2 = x[2 * NTOK + r0];
    const float xB0 = x[r0 + 8],  xB1 = x[NTOK + r0 + 8],  xB2 = x[2 * NTOK + r0 + 8];
    const float xC0 = x[r0 + 16], xC1 = x[NTOK + r0 + 16], xC2 = x[2 * NTOK + r0 + 16];
    const float xD0 = x[r0 + 24], xD1 = x[NTOK + r0 + 24], xD2 = x[2 * NTOK + r0 + 24];
    __syncthreads();

    const int par = g & 1;
    const int ib = warp * 32 + g + 2 * t - par;
    const float* sb = band + (par ? ODD_OFF : 0);
    const float2* p0 = (const float2*)(sb + ib);
    const float2* p1 = (const float2*)(sb + BANDLEN + ib);
    const float2* p2 = (const float2*)(sb + 2 * BANDLEN + ib);

    const uint4* bp = (const uint4*)g_w1p + (size_t)(kq * 128) * 128 + lane * 4;

    float acc[2][8][4];
    #pragma unroll
    for (int s = 0; s < 2; s++)
        #pragma unroll
        for (int nt = 0; nt < 8; nt++)
            #pragma unroll
            for (int k = 0; k < 4; k++) acc[s][nt][k] = 0.f;

    float2 u0 = p0[0], u1 = p0[4], u2 = p0[8];
    float2 v0 = p1[0], v1 = p1[4], v2 = p1[8];
    float2 w0 = p2[0], w1 = p2[4], w2 = p2[8];

    #pragma unroll 2
    for (int ks = 0; ks < 128; ks++) {
        const int e = ks * 8;
        const float2 u3 = p0[e + 12], u4 = p0[e + 16];
        const float2 v3 = p1[e + 12], v4 = p1[e + 16];
        const float2 w3 = p2[e + 12], w4 = p2[e + 16];

        const float d0lo = fmaf(xA0, u0.x, fmaf(xA1, v0.x, xA2 * w0.x));
        const float d0hi = fmaf(xA0, u0.y, fmaf(xA1, v0.y, xA2 * w0.y));
        const float d1lo = fmaf(xA0, u1.x, fmaf(xA1, v1.x, xA2 * w1.x));
        const float d1hi = fmaf(xA0, u1.y, fmaf(xA1, v1.y, xA2 * w1.y));
        const float e1lo = fmaf(xB0, u1.x, fmaf(xB1, v1.x, xB2 * w1.x));
        const float e1hi = fmaf(xB0, u1.y, fmaf(xB1, v1.y, xB2 * w1.y));
        const float e2lo = fmaf(xB0, u2.x, fmaf(xB1, v2.x, xB2 * w2.x));
        const float e2hi = fmaf(xB0, u2.y, fmaf(xB1, v2.y, xB2 * w2.y));
        const float f2lo = fmaf(xC0, u2.x, fmaf(xC1, v2.x, xC2 * w2.x));
        const float f2hi = fmaf(xC0, u2.y, fmaf(xC1, v2.y, xC2 * w2.y));
        const float f3lo = fmaf(xC0, u3.x, fmaf(xC1, v3.x, xC2 * w3.x));
        const float f3hi = fmaf(xC0, u3.y, fmaf(xC1, v3.y, xC2 * w3.y));
        const float h3lo = fmaf(xD0, u3.x, fmaf(xD1, v3.x, xD2 * w3.x));
        const float h3hi = fmaf(xD0, u3.y, fmaf(xD1, v3.y, xD2 * w3.y));
        const float h4lo = fmaf(xD0, u4.x, fmaf(xD1, v4.x, xD2 * w4.x));
        const float h4hi = fmaf(xD0, u4.y, fmaf(xD1, v4.y, xD2 * w4.y));

        const uint32_t a0 = pack_bf16x2(d0lo, d0hi);
        const uint32_t a1 = pack_bf16x2(e1lo, e1hi);
        const uint32_t a2 = pack_bf16x2(d1lo, d1hi);
        const uint32_t a3 = pack_bf16x2(e2lo, e2hi);
        const uint32_t c0 = pack_bf16x2(f2lo, f2hi);
        const uint32_t c1 = pack_bf16x2(h3lo, h3hi);
        const uint32_t c2 = pack_bf16x2(f3lo, f3hi);
        const uint32_t c3 = pack_bf16x2(h4lo, h4hi);

        const uint4 B0 = bp[0], B1 = bp[1], B2 = bp[2], B3 = bp[3];
        bp += 128;

        MMA_BF16(acc[0][0][0], acc[0][0][1], acc[0][0][2], acc[0][0][3], a0, a1, a2, a3, B0.x, B0.y);
        MMA_BF16(acc[0][1][0], acc[0][1][1], acc[0][1][2], acc[0][1][3], a0, a1, a2, a3, B0.z, B0.w);
        MMA_BF16(acc[0][2][0], acc[0][2][1], acc[0][2][2], acc[0][2][3], a0, a1, a2, a3, B1.x, B1.y);
        MMA_BF16(acc[0][3][0], acc[0][3][1], acc[0][3][2], acc[0][3][3], a0, a1, a2, a3, B1.z, B1.w);
        MMA_BF16(acc[0][4][0], acc[0][4][1], acc[0][4][2], acc[0][4][3], a0, a1, a2, a3, B2.x, B2.y);
        MMA_BF16(acc[0][5][0], acc[0][5][1], acc[0][5][2], acc[0][5][3], a0, a1, a2, a3, B2.z, B2.w);
        MMA_BF16(acc[0][6][0], acc[0][6][1], acc[0][6][2], acc[0][6][3], a0, a1, a2, a3, B3.x, B3.y);
        MMA_BF16(acc[0][7][0], acc[0][7][1], acc[0][7][2], acc[0][7][3], a0, a1, a2, a3, B3.z, B3.w);

        MMA_BF16(acc[1][0][0], acc[1][0][1], acc[1][0][2], acc[1][0][3], c0, c1, c2, c3, B0.x, B0.y);
        MMA_BF16(acc[1][1][0], acc[1][1][1], acc[1][1][2], acc[1][1][3], c0, c1, c2, c3, B0.z, B0.w);
        MMA_BF16(acc[1][2][0], acc[1][2][1], acc[1][2][2], acc[1][2][3], c0, c1, c2, c3, B1.x, B1.y);
        MMA_BF16(acc[1][3][0], acc[1][3][1], acc[1][3][2], acc[1][3][3], c0, c1, c2, c3, B1.z, B1.w);
        MMA_BF16(acc[1][4][0], acc[1][4][1], acc[1][4][2], acc[1][4][3], c0, c1, c2, c3, B2.x, B2.y);
        MMA_BF16(acc[1][5][0], acc[1][5][1], acc[1][5][2], acc[1][5][3], c0, c1, c2, c3, B2.z, B2.w);
        MMA_BF16(acc[1][6][0], acc[1][6][1], acc[1][6][2], acc[1][6][3], c0, c1, c2, c3, B3.x, B3.y);
        MMA_BF16(acc[1][7][0], acc[1][7][1], acc[1][7][2], acc[1][7][3], c0, c1, c2, c3, B3.z, B3.w);

        u0 = u2; u1 = u3; u2 = u4;
        v0 = v2; v1 = v3; v2 = v4;
        w0 = w2; w1 = w3; w2 = w4;
    }

    // epilogue: [kq][row][f] layout, float2 stores
    float* basep = g_partial + (size_t)kq * (NTOK * 64);
    #pragma unroll
    for (int s = 0; s < 2; s++) {
        const int rA = r0 + 16 * s, rB = rA + 8;
        #pragma unroll
        for (int nt = 0; nt < 8; nt++) {
            const int n = nt * 8 + 2 * t;
            *(float2*)(basep + (size_t)rA * 64 + n) = make_float2(acc[s][nt][0], acc[s][nt][1]);
            *(float2*)(basep + (size_t)rB * 64 + n) = make_float2(acc[s][nt][2], acc[s][nt][3]);
        }
    }
}

// ---------------------------------------------------------------------------
// K4: per-row MLP epilogue, warp-per-row + final combine (last block)
//   grid = 256 x 256 threads (8 warps); warp handles 4 rows.
// ---------------------------------------------------------------------------
__global__ __launch_bounds__(256) void mlp_kernel(const float* __restrict__ W2,
                                                  const float* __restrict__ W3,
                                                  const float* __restrict__ regu2,
                                                  const float* __restrict__ regu,
                                                  float* __restrict__ out) {
    __shared__ float w2s[4096];
    __shared__ float w3s[64];
    __shared__ float z1s[8][64];
    __shared__ float wsum[8];
    const int tid = threadIdx.x, warp = tid >> 5, lane = tid & 31;
    for (int tv = tid; tv < 4096; tv += 256) w2s[tv] = W2[tv];
    if (tid < 64) w3s[tid] = W3[tid];
    __syncthreads();

    float local = 0.f;
    #pragma unroll
    for (int rr = 0; rr < 4; rr++) {
        const int row = blockIdx.x * 32 + rr * 8 + warp;
        // preact: sum of 4 quarters, float2 per lane (coalesced 256B/warp)
        float2 pre = make_float2(0.f, 0.f);
        #pragma unroll
        for (int q = 0; q < 4; q++) {
            const float2 p = ((const float2*)(g_partial + (size_t)q * NTOK * 64 + (size_t)row * 64))[lane];
            pre.x += p.x; pre.y += p.y;
        }
        z1s[warp][2 * lane]     = elu1(pre.x);
        z1s[warp][2 * lane + 1] = elu1(pre.y);
        __syncwarp();

        float2 acc = make_float2(0.f, 0.f);
        #pragma unroll
        for (int f1 = 0; f1 < 64; f1++) {
            const float z = z1s[warp][f1];                       // broadcast LDS
            const float2 w = ((const float2*)(w2s + f1 * 64))[lane];
            acc.x = fmaf(z, w.x, acc.x);
            acc.y = fmaf(z, w.y, acc.y);
        }
        float z3 = fmaf(elu1(acc.x), w3s[2 * lane], elu1(acc.y) * w3s[2 * lane + 1]);
        #pragma unroll
        for (int o = 16; o > 0; o >>= 1) z3 += __shfl_down_sync(0xFFFFFFFFu, z3, o);
        if (lane == 0) local += elu1(z3);
        __syncwarp();
    }
    if (lane == 0) wsum[warp] = local;
    __syncthreads();
    if (tid == 0) {
        float s = 0.f;
        #pragma unroll
        for (int wv = 0; wv < 8; wv++) s += wsum[wv];
        atomicAdd(&g_acc[2], (double)s);
        __threadfence();
        const unsigned int done = atomicAdd(&g_done, 1u);
        if (done == gridDim.x - 1) {
            const double s0 = atomicAdd(&g_acc[0], 0.0);
            const double s1 = atomicAdd(&g_acc[1], 0.0);
            const double s2 = atomicAdd(&g_acc[2], 0.0);
            out[0] = (float)(s2 / (double)NTOK
                             - (double)regu2[0] * s0
                             - (double)regu[0] * s1);
        }
    }
}

// ---------------------------------------------------------------------------
// kernel_launch   d_in: 0=x 1=W1 2=W2 3=W3 4=regu2 5=regu 6=regu_length
// ---------------------------------------------------------------------------
extern "C" void kernel_launch(void* const* d_in, const int* in_sizes, int n_in,
                              void* d_out, int out_size) {
    const float* x  = (const float*)d_in[0];
    const float* W1 = (const float*)d_in[1];
    const float* W2 = (const float*)d_in[2];
    const float* W3 = (const float*)d_in[3];
    const float* r2 = (const float*)d_in[4];
    const float* r  = (const float*)d_in[5];
    const float* rl = (const float*)d_in[6];
    float* out = (float*)d_out;

    static const int smem_bytes = (6 * BANDLEN + 16) * sizeof(float);   // 56128
    cudaFuncSetAttribute(gemm_kernel, cudaFuncAttributeMaxDynamicSharedMemorySize, smem_bytes);

    w1prep_kernel<<<256, 256>>>(W1);      // also zeroes g_acc / g_done
    reg_kernel<<<8, 1024>>>(x, rl);
    gemm_kernel<<<128, 256, smem_bytes>>>(x);
    mlp_kernel<<<256, 256>>>(W2, W3, r2, r, out);
}

// round 6
// speedup vs baseline: 1.5819x; 1.5819x over previous
#include <cuda_runtime.h>
#include <cuda_bf16.h>
#include <cstdint>

// ============================================================================
//   x : (3, 8192) fp32   W1 : (8192, 64)   W2 : (64, 64)   W3 : (64, 1)
//   out = mean(per_row MLP(corr)) - regu2*sum(x2) - regu*sum(exp(x2/(2 rl^2)))
//   corr[i,j] = sum_c x[c,(i+j)%N] * x[c,i]
//
//   R6: mlp rebuilt (prefetched preacts, 4 rows fused per f1-iteration),
//   reg reductions folded into mlp, 3 launches total. gemm unchanged (control).
// ============================================================================
#define NTOK 8192
#define KQUART 2048
#define BANDLEN 2336                     // 2048 + 256 + slack, mult of 32
#define ODD_OFF (3 * BANDLEN + 16)       // +16 floats: disjoint banks vs even

__device__ double g_acc[3];                               // sum_x2, sum_exp, sum_per_row
__device__ unsigned int g_done;                           // mlp completion counter
__device__ __align__(16) float g_partial[4 * NTOK * 64];  // [kq][row][f], 8MB
__device__ __align__(16) uint32_t g_w1p[512 * 32 * 16];   // [ks][lane][nt*2+r] bf16x2

__device__ __forceinline__ uint32_t pack_bf16x2(float lo, float hi) {
    uint32_t r;
    asm("cvt.rn.bf16x2.f32 %0, %1, %2;" : "=r"(r) : "f"(hi), "f"(lo));
    return r;
}
__device__ __forceinline__ float elu1(float v) { return v > 0.f ? v : expm1f(v); }

#define MMA_BF16(d0,d1,d2,d3,a0,a1,a2,a3,b0,b1) \
    asm volatile("mma.sync.aligned.m16n8k16.row.col.f32.bf16.bf16.f32 " \
                 "{%0,%1,%2,%3}, {%4,%5,%6,%7}, {%8,%9}, {%0,%1,%2,%3};" \
                 : "+f"(d0), "+f"(d1), "+f"(d2), "+f"(d3) \
                 : "r"(a0), "r"(a1), "r"(a2), "r"(a3), "r"(b0), "r"(b1))

// ---------------------------------------------------------------------------
// K1: W1 -> m16n8k16 B fragments (coalesced via smem). Block 0 zeroes accums.
// ---------------------------------------------------------------------------
__global__ __launch_bounds__(256) void w1prep_kernel(const float* __restrict__ W1) {
    __shared__ float w[2048];
    if (blockIdx.x == 0 && threadIdx.x == 0) {
        g_acc[0] = 0.0; g_acc[1] = 0.0; g_acc[2] = 0.0; g_done = 0u;
    }
    const int b = blockIdx.x, tid = threadIdx.x;
    const float* src = W1 + b * 2048;                 // rows [32b, 32b+32) x 64
    #pragma unroll
    for (int i = 0; i < 8; i++) w[tid + i * 256] = src[tid + i * 256];
    __syncthreads();

    uint32_t o4[4];
    #pragma unroll
    for (int j = 0; j < 4; j++) {
        const int o = tid * 4 + j;                    // 0..1023
        const int ksl = o >> 9;
        const int rest = o & 511;
        const int lane = rest >> 4;
        const int q = rest & 15;
        const int nt = q >> 1, r = q & 1;
        const int k = ksl * 16 + (lane & 3) * 2 + r * 8;
        const int n = nt * 8 + (lane >> 2);
        o4[j] = pack_bf16x2(w[k * 64 + n], w[(k + 1) * 64 + n]);
    }
    ((uint4*)g_w1p)[b * 256 + tid] = make_uint4(o4[0], o4[1], o4[2], o4[3]);
}

// ---------------------------------------------------------------------------
// K2: fused corr-build + mma.sync bf16 GEMM (preact = corr @ W1) — unchanged
//   grid = 128: (i-tile of 256 rows) x (K-quarter of 2048)
// ---------------------------------------------------------------------------
__global__ __launch_bounds__(256, 1) void gemm_kernel(const float* __restrict__ x) {
    extern __shared__ float band[];                   // even[3][BANDLEN] | pad16 | odd[3][BANDLEN]
    const int tid = threadIdx.x, warp = tid >> 5, lane = tid & 31;
    const int g = lane >> 2, t = lane & 3;
    const int it = blockIdx.x >> 2, kq = blockIdx.x & 3;
    const int i0 = it * 256, jbase = kq * KQUART;

    for (int o = tid; o < BANDLEN; o += 256) {
        const int s0 = (i0 + jbase + o) & (NTOK - 1);
        const int s1 = (i0 + jbase + o + 1) & (NTOK - 1);
        band[o]                         = x[s0];
        band[BANDLEN + o]               = x[NTOK + s0];
        band[2 * BANDLEN + o]           = x[2 * NTOK + s0];
        band[ODD_OFF + o]               = x[s1];
        band[ODD_OFF + BANDLEN + o]     = x[NTOK + s1];
        band[ODD_OFF + 2 * BANDLEN + o] = x[2 * NTOK + s1];
    }
    const int r0 = i0 + warp * 32 + g;
    const float xA0 = x[r0],      xA1 = x[NTOK + r0],      xA2 = x[2 * NTOK + r0];
    const float xB0 = x[r0 + 8],  xB1 = x[NTOK + r0 + 8],  xB2 = x[2 * NTOK + r0 + 8];
    const float xC0 = x[r0 + 16], xC1 = x[NTOK + r0 + 16], xC2 = x[2 * NTOK + r0 + 16];
    const float xD0 = x[r0 + 24], xD1 = x[NTOK + r0 + 24], xD2 = x[2 * NTOK + r0 + 24];
    __syncthreads();

    const int par = g & 1;
    const int ib = warp * 32 + g + 2 * t - par;
    const float* sb = band + (par ? ODD_OFF : 0);
    const float2* p0 = (const float2*)(sb + ib);
    const float2* p1 = (const float2*)(sb + BANDLEN + ib);
    const float2* p2 = (const float2*)(sb + 2 * BANDLEN + ib);

    const uint4* bp = (const uint4*)g_w1p + (size_t)(kq * 128) * 128 + lane * 4;

    float acc[2][8][4];
    #pragma unroll
    for (int s = 0; s < 2; s++)
        #pragma unroll
        for (int nt = 0; nt < 8; nt++)
            #pragma unroll
            for (int k = 0; k < 4; k++) acc[s][nt][k] = 0.f;

    float2 u0 = p0[0], u1 = p0[4], u2 = p0[8];
    float2 v0 = p1[0], v1 = p1[4], v2 = p1[8];
    float2 w0 = p2[0], w1 = p2[4], w2 = p2[8];

    #pragma unroll 2
    for (int ks = 0; ks < 128; ks++) {
        const int e = ks * 8;
        const float2 u3 = p0[e + 12], u4 = p0[e + 16];
        const float2 v3 = p1[e + 12], v4 = p1[e + 16];
        const float2 w3 = p2[e + 12], w4 = p2[e + 16];

        const float d0lo = fmaf(xA0, u0.x, fmaf(xA1, v0.x, xA2 * w0.x));
        const float d0hi = fmaf(xA0, u0.y, fmaf(xA1, v0.y, xA2 * w0.y));
        const float d1lo = fmaf(xA0, u1.x, fmaf(xA1, v1.x, xA2 * w1.x));
        const float d1hi = fmaf(xA0, u1.y, fmaf(xA1, v1.y, xA2 * w1.y));
        const float e1lo = fmaf(xB0, u1.x, fmaf(xB1, v1.x, xB2 * w1.x));
        const float e1hi = fmaf(xB0, u1.y, fmaf(xB1, v1.y, xB2 * w1.y));
        const float e2lo = fmaf(xB0, u2.x, fmaf(xB1, v2.x, xB2 * w2.x));
        const float e2hi = fmaf(xB0, u2.y, fmaf(xB1, v2.y, xB2 * w2.y));
        const float f2lo = fmaf(xC0, u2.x, fmaf(xC1, v2.x, xC2 * w2.x));
        const float f2hi = fmaf(xC0, u2.y, fmaf(xC1, v2.y, xC2 * w2.y));
        const float f3lo = fmaf(xC0, u3.x, fmaf(xC1, v3.x, xC2 * w3.x));
        const float f3hi = fmaf(xC0, u3.y, fmaf(xC1, v3.y, xC2 * w3.y));
        const float h3lo = fmaf(xD0, u3.x, fmaf(xD1, v3.x, xD2 * w3.x));
        const float h3hi = fmaf(xD0, u3.y, fmaf(xD1, v3.y, xD2 * w3.y));
        const float h4lo = fmaf(xD0, u4.x, fmaf(xD1, v4.x, xD2 * w4.x));
        const float h4hi = fmaf(xD0, u4.y, fmaf(xD1, v4.y, xD2 * w4.y));

        const uint32_t a0 = pack_bf16x2(d0lo, d0hi);
        const uint32_t a1 = pack_bf16x2(e1lo, e1hi);
        const uint32_t a2 = pack_bf16x2(d1lo, d1hi);
        const uint32_t a3 = pack_bf16x2(e2lo, e2hi);
        const uint32_t c0 = pack_bf16x2(f2lo, f2hi);
        const uint32_t c1 = pack_bf16x2(h3lo, h3hi);
        const uint32_t c2 = pack_bf16x2(f3lo, f3hi);
        const uint32_t c3 = pack_bf16x2(h4lo, h4hi);

        const uint4 B0 = bp[0], B1 = bp[1], B2 = bp[2], B3 = bp[3];
        bp += 128;

        MMA_BF16(acc[0][0][0], acc[0][0][1], acc[0][0][2], acc[0][0][3], a0, a1, a2, a3, B0.x, B0.y);
        MMA_BF16(acc[0][1][0], acc[0][1][1], acc[0][1][2], acc[0][1][3], a0, a1, a2, a3, B0.z, B0.w);
        MMA_BF16(acc[0][2][0], acc[0][2][1], acc[0][2][2], acc[0][2][3], a0, a1, a2, a3, B1.x, B1.y);
        MMA_BF16(acc[0][3][0], acc[0][3][1], acc[0][3][2], acc[0][3][3], a0, a1, a2, a3, B1.z, B1.w);
        MMA_BF16(acc[0][4][0], acc[0][4][1], acc[0][4][2], acc[0][4][3], a0, a1, a2, a3, B2.x, B2.y);
        MMA_BF16(acc[0][5][0], acc[0][5][1], acc[0][5][2], acc[0][5][3], a0, a1, a2, a3, B2.z, B2.w);
        MMA_BF16(acc[0][6][0], acc[0][6][1], acc[0][6][2], acc[0][6][3], a0, a1, a2, a3, B3.x, B3.y);
        MMA_BF16(acc[0][7][0], acc[0][7][1], acc[0][7][2], acc[0][7][3], a0, a1, a2, a3, B3.z, B3.w);

        MMA_BF16(acc[1][0][0], acc[1][0][1], acc[1][0][2], acc[1][0][3], c0, c1, c2, c3, B0.x, B0.y);
        MMA_BF16(acc[1][1][0], acc[1][1][1], acc[1][1][2], acc[1][1][3], c0, c1, c2, c3, B0.z, B0.w);
        MMA_BF16(acc[1][2][0], acc[1][2][1], acc[1][2][2], acc[1][2][3], c0, c1, c2, c3, B1.x, B1.y);
        MMA_BF16(acc[1][3][0], acc[1][3][1], acc[1][3][2], acc[1][3][3], c0, c1, c2, c3, B1.z, B1.w);
        MMA_BF16(acc[1][4][0], acc[1][4][1], acc[1][4][2], acc[1][4][3], c0, c1, c2, c3, B2.x, B2.y);
        MMA_BF16(acc[1][5][0], acc[1][5][1], acc[1][5][2], acc[1][5][3], c0, c1, c2, c3, B2.z, B2.w);
        MMA_BF16(acc[1][6][0], acc[1][6][1], acc[1][6][2], acc[1][6][3], c0, c1, c2, c3, B3.x, B3.y);
        MMA_BF16(acc[1][7][0], acc[1][7][1], acc[1][7][2], acc[1][7][3], c0, c1, c2, c3, B3.z, B3.w);

        u0 = u2; u1 = u3; u2 = u4;
        v0 = v2; v1 = v3; v2 = v4;
        w0 = w2; w1 = w3; w2 = w4;
    }

    // epilogue: [kq][row][f] layout; quad-contiguous 32B-sector float2 stores
    float* basep = g_partial + (size_t)kq * (NTOK * 64);
    #pragma unroll
    for (int s = 0; s < 2; s++) {
        const int rA = r0 + 16 * s, rB = rA + 8;
        #pragma unroll
        for (int nt = 0; nt < 8; nt++) {
            const int n = nt * 8 + 2 * t;
            *(float2*)(basep + (size_t)rA * 64 + n) = make_float2(acc[s][nt][0], acc[s][nt][1]);
            *(float2*)(basep + (size_t)rB * 64 + n) = make_float2(acc[s][nt][2], acc[s][nt][3]);
        }
    }
}

// ---------------------------------------------------------------------------
// K3: MLP epilogue + regularization + final combine.
//   grid = 256 CTAs x 256 thr. Block owns 32 rows; warp owns 4 rows fused.
//   Warp 0 additionally computes x2/exp sums for the block's 32 tokens.
// ---------------------------------------------------------------------------
__global__ __launch_bounds__(256) void mlp_kernel(const float* __restrict__ x,
                                                  const float* __restrict__ W2,
                                                  const float* __restrict__ W3,
                                                  const float* __restrict__ regu2,
                                                  const float* __restrict__ regu,
                                                  const float* __restrict__ rl_p,
                                                  float* __restrict__ out) {
    __shared__ float w2s[4096];
    __shared__ float w3s[64];
    __shared__ float z1s[32][64];
    __shared__ float wsum[8];
    __shared__ float rsum[2];
    const int tid = threadIdx.x, warp = tid >> 5, lane = tid & 31;

    // regularization for this block's 32 tokens (warp 0 only)
    if (warp == 0) {
        const int tok = blockIdx.x * 32 + lane;
        const float a = x[tok], b = x[NTOK + tok], c = x[2 * NTOK + tok];
        float x2 = fmaf(a, a, fmaf(b, b, c * c));
        const float rl = rl_p[0];
        float e = expf(x2 / (2.f * rl * rl));
        #pragma unroll
        for (int o = 16; o > 0; o >>= 1) {
            x2 += __shfl_down_sync(0xFFFFFFFFu, x2, o);
            e  += __shfl_down_sync(0xFFFFFFFFu, e, o);
        }
        if (lane == 0) { rsum[0] = x2; rsum[1] = e; }
    }

    for (int tv = tid; tv < 4096; tv += 256) w2s[tv] = W2[tv];
    if (tid < 64) w3s[tid] = W3[tid];

    // prefetch preacts: 4 rows x 4 quarters, independent float2 loads
    const int rbase = blockIdx.x * 32 + warp * 4;
    float2 pq[4][4];
    #pragma unroll
    for (int rr = 0; rr < 4; rr++)
        #pragma unroll
        for (int q = 0; q < 4; q++)
            pq[rr][q] = ((const float2*)(g_partial + ((size_t)q * NTOK + rbase + rr) * 64))[lane];

    #pragma unroll
    for (int rr = 0; rr < 4; rr++) {
        const float px = pq[rr][0].x + pq[rr][1].x + pq[rr][2].x + pq[rr][3].x;
        const float py = pq[rr][0].y + pq[rr][1].y + pq[rr][2].y + pq[rr][3].y;
        z1s[warp * 4 + rr][2 * lane]     = elu1(px);
        z1s[warp * 4 + rr][2 * lane + 1] = elu1(py);
    }
    __syncthreads();      // w2s/w3s + z1s ready

    // fused 4-row layer-2: per f1, 1 w2 float2 + 4 z broadcasts + 8 FMA
    float2 a0 = make_float2(0.f, 0.f), a1 = a0, a2 = a0, a3 = a0;
    const float2* w2p = (const float2*)w2s + lane;
    const float* z0p = z1s[warp * 4 + 0];
    const float* z1p = z1s[warp * 4 + 1];
    const float* z2p = z1s[warp * 4 + 2];
    const float* z3p = z1s[warp * 4 + 3];
    #pragma unroll 8
    for (int f1 = 0; f1 < 64; f1++) {
        const float2 w = w2p[f1 * 32];
        const float za = z0p[f1], zb = z1p[f1], zc = z2p[f1], zd = z3p[f1];
        a0.x = fmaf(za, w.x, a0.x); a0.y = fmaf(za, w.y, a0.y);
        a1.x = fmaf(zb, w.x, a1.x); a1.y = fmaf(zb, w.y, a1.y);
        a2.x = fmaf(zc, w.x, a2.x); a2.y = fmaf(zc, w.y, a2.y);
        a3.x = fmaf(zd, w.x, a3.x); a3.y = fmaf(zd, w.y, a3.y);
    }

    // layer-3 + per-row elu, warp reductions
    const float w3a = w3s[2 * lane], w3b = w3s[2 * lane + 1];
    float s0 = fmaf(elu1(a0.x), w3a, elu1(a0.y) * w3b);
    float s1 = fmaf(elu1(a1.x), w3a, elu1(a1.y) * w3b);
    float s2 = fmaf(elu1(a2.x), w3a, elu1(a2.y) * w3b);
    float s3 = fmaf(elu1(a3.x), w3a, elu1(a3.y) * w3b);
    #pragma unroll
    for (int o = 16; o > 0; o >>= 1) {
        s0 += __shfl_down_sync(0xFFFFFFFFu, s0, o);
        s1 += __shfl_down_sync(0xFFFFFFFFu, s1, o);
        s2 += __shfl_down_sync(0xFFFFFFFFu, s2, o);
        s3 += __shfl_down_sync(0xFFFFFFFFu, s3, o);
    }
    if (lane == 0) wsum[warp] = elu1(s0) + elu1(s1) + elu1(s2) + elu1(s3);
    __syncthreads();

    if (tid == 0) {
        float s = 0.f;
        #pragma unroll
        for (int wv = 0; wv < 8; wv++) s += wsum[wv];
        atomicAdd(&g_acc[2], (double)s);
        atomicAdd(&g_acc[0], (double)rsum[0]);
        atomicAdd(&g_acc[1], (double)rsum[1]);
        __threadfence();
        const unsigned int done = atomicAdd(&g_done, 1u);
        if (done == gridDim.x - 1) {
            const double t0 = atomicAdd(&g_acc[0], 0.0);
            const double t1 = atomicAdd(&g_acc[1], 0.0);
            const double t2 = atomicAdd(&g_acc[2], 0.0);
            out[0] = (float)(t2 / (double)NTOK
                             - (double)regu2[0] * t0
                             - (double)regu[0] * t1);
        }
    }
}

// ---------------------------------------------------------------------------
// kernel_launch   d_in: 0=x 1=W1 2=W2 3=W3 4=regu2 5=regu 6=regu_length
// ---------------------------------------------------------------------------
extern "C" void kernel_launch(void* const* d_in, const int* in_sizes, int n_in,
                              void* d_out, int out_size) {
    const float* x  = (const float*)d_in[0];
    const float* W1 = (const float*)d_in[1];
    const float* W2 = (const float*)d_in[2];
    const float* W3 = (const float*)d_in[3];
    const float* r2 = (const float*)d_in[4];
    const float* r  = (const float*)d_in[5];
    const float* rl = (const float*)d_in[6];
    float* out = (float*)d_out;

    static const int smem_bytes = (6 * BANDLEN + 16) * sizeof(float);   // 56128
    cudaFuncSetAttribute(gemm_kernel, cudaFuncAttributeMaxDynamicSharedMemorySize, smem_bytes);

    w1prep_kernel<<<256, 256>>>(W1);      // also zeroes g_acc / g_done
    gemm_kernel<<<128, 256, smem_bytes>>>(x);
    mlp_kernel<<<256, 256>>>(x, W2, W3, r2, r, rl, out);
}